// round 14
// baseline (speedup 1.0000x reference)
#include <cuda_runtime.h>
#include <cuda_fp16.h>
#include <cstdint>

// Shapes fixed by dataset: q/k (4,16,4096,64) f32, cos/sin (4,4096,64) f32, vs (32,64) f32
#define DD 64
#define SSS 4096
#define NROWS_Q (4*16*4096)    // 262144
#define NROWS_T (2*NROWS_Q)    // 524288
#define NREFL 32

// Dynamic smem layout (floats):
//   [0, 8704)      xs: O staging (128 x 68); ALSO scan workspace (vsh 2048 | Qs 4096)
//   [8704, 9248)   cs (8 x 68)
//   [9248, 9792)   ss (8 x 68)
//   [9792, 11840)  B1 frags (512 uint4)
//   [11840, 13888) B2 frags (512 uint4)
#define SM_XS   0
#define SM_CS   8704
#define SM_SS   9248
#define SM_B1   9792
#define SM_B2   11840
#define SMEM_FLOATS 13888      // 55552 bytes
#define XS_STRIDE 68

__device__ __forceinline__ uint32_t pk_f16x2(float a, float b) {
    __half2 h = __floats2half2_rn(a, b);
    return *(uint32_t*)&h;
}

#define MMA_F16(c, a0, a1, a2, a3, b0, b1)                                         \
    asm volatile("mma.sync.aligned.m16n8k16.row.col.f32.f16.f16.f32 "              \
                 "{%0,%1,%2,%3}, {%4,%5,%6,%7}, {%8,%9}, {%0,%1,%2,%3};"           \
                 : "+f"(c[0]), "+f"(c[1]), "+f"(c[2]), "+f"(c[3])                   \
                 : "r"(a0), "r"(a1), "r"(a2), "r"(a3), "r"(b0), "r"(b1))

// ---------------- fused kernel (ONE launch, grid 4096, one chunk per block) ----------------
// Phase 0 (every block, redundant): barrier-free column-owner Householder scan ->
//          Q in smem -> pack fp16 B fragments (both GEMM layouts) into smem.
//          Scan is latency-bound and issue-light; it hides in the ~80% idle issue slots.
// Phase 1: R12 body: A1 direct from GMEM (K-permuted GEMM1), rope in fragments,
//          GEMM2 from register A2, O via smem flush.
__global__ void __launch_bounds__(128, 4) rnrope_fused_kernel(
    const float* __restrict__ qin, const float* __restrict__ kin,
    const float* __restrict__ cosp, const float* __restrict__ sinp,
    const float* __restrict__ vs, float* __restrict__ out)
{
    extern __shared__ __align__(16) float sm[];
    __shared__ float coefs[NREFL];

    const int tid  = threadIdx.x;
    const int warp = tid >> 5;
    const int lane = tid & 31;
    const int g    = lane >> 2;
    const int t4   = lane & 3;

    // ================= Phase 0: build Q + pack B fragments =================
    {
        float* vsh = sm + SM_XS;          // 2048 floats (aliases xs)
        float* Qs  = sm + SM_XS + 2048;   // 4096 floats (aliases xs)

        for (int i = tid; i < NREFL*DD/4; i += 128)
            ((float4*)vsh)[i] = ((const float4*)vs)[i];
        __syncthreads();
        if (tid < NREFL) {
            float s = 0.0f;
            const float4* v4 = (const float4*)&vsh[tid*DD];
            #pragma unroll
            for (int c = 0; c < 16; ++c) {
                float4 v = v4[c];
                s += v.x*v.x + v.y*v.y + v.z*v.z + v.w*v.w;
            }
            coefs[tid] = 2.0f / (s + 1e-8f);
        }
        __syncthreads();

        // column-owner scan: column j of Q evolves independently.
        // Thread owns 32 rows of one column in registers; partner (lane^16) the rest.
        const int col = (warp << 4) | (lane & 15);   // 0..63
        const int seg = lane >> 4;                   // 0: rows 0-31, 1: rows 32-63
        float qc[32];
        #pragma unroll
        for (int i = 0; i < 32; ++i) qc[i] = (seg*32 + i == col) ? 1.0f : 0.0f;

        for (int r = 0; r < NREFL; ++r) {
            const float4* v4 = (const float4*)&vsh[r*DD + seg*32];
            float4 vv[8];
            #pragma unroll
            for (int i = 0; i < 8; ++i) vv[i] = v4[i];
            float w0 = 0.f, w1 = 0.f, w2 = 0.f, w3 = 0.f;
            #pragma unroll
            for (int i = 0; i < 8; ++i) {
                w0 += vv[i].x * qc[4*i];
                w1 += vv[i].y * qc[4*i+1];
                w2 += vv[i].z * qc[4*i+2];
                w3 += vv[i].w * qc[4*i+3];
            }
            float w = (w0 + w1) + (w2 + w3);
            w += __shfl_xor_sync(0xffffffffu, w, 16);
            float cw = coefs[r] * w;
            #pragma unroll
            for (int i = 0; i < 8; ++i) {
                qc[4*i]   -= vv[i].x * cw;
                qc[4*i+1] -= vv[i].y * cw;
                qc[4*i+2] -= vv[i].z * cw;
                qc[4*i+3] -= vv[i].w * cw;
            }
        }
        #pragma unroll
        for (int i = 0; i < 32; ++i) Qs[(seg*32 + i)*DD + col] = qc[i];
        __syncthreads();

        // pack B fragments into smem (uint4 = {b0_even_nt, b1_even_nt, b0_odd_nt, b1_odd_nt})
        uint4* B1 = (uint4*)(sm + SM_B1);
        uint4* B2 = (uint4*)(sm + SM_B2);
        for (int slot = tid; slot < 512; slot += 128) {
            int l2 = slot & 31, idx = slot >> 5;     // idx = kt*4 + nt2
            int kt = idx >> 2, nt2 = idx & 3;
            int gg = l2 >> 2, tt4 = l2 & 3;
            int ne = 16*nt2 + gg;
            int no = ne + 8;
            // B1: K-permuted (GEMM1), C0 = 16kt + 4t4, pairs (C0,C0+1),(C0+2,C0+3)
            {
                int C0 = 16*kt + 4*tt4;
                uint4 v;
                v.x = pk_f16x2(Qs[ne*DD + C0],     Qs[ne*DD + C0 + 1]);
                v.y = pk_f16x2(Qs[ne*DD + C0 + 2], Qs[ne*DD + C0 + 3]);
                v.z = pk_f16x2(Qs[no*DD + C0],     Qs[no*DD + C0 + 1]);
                v.w = pk_f16x2(Qs[no*DD + C0 + 2], Qs[no*DD + C0 + 3]);
                B1[slot] = v;
            }
            // B2: standard m16n8k16 (GEMM2), element (k, n) = Q[k][n]
            {
                int k0 = 16*kt + 2*tt4;
                uint4 v;
                v.x = pk_f16x2(Qs[k0*DD + ne],     Qs[(k0+1)*DD + ne]);
                v.y = pk_f16x2(Qs[(k0+8)*DD + ne], Qs[(k0+9)*DD + ne]);
                v.z = pk_f16x2(Qs[k0*DD + no],     Qs[(k0+1)*DD + no]);
                v.w = pk_f16x2(Qs[(k0+8)*DD + no], Qs[(k0+9)*DD + no]);
                B2[slot] = v;
            }
        }
        __syncthreads();   // B frags complete; Qs/vsh (xs) region free
    }

    float* xs = sm + SM_XS;
    float* cs = sm + SM_CS;
    float* ss = sm + SM_SS;
    const uint4* B1 = (const uint4*)(sm + SM_B1);
    const uint4* B2 = (const uint4*)(sm + SM_B2);

    // ================= Phase 1: one chunk (R12 body) =================
    const int bid    = blockIdx.x;            // 4096 blocks
    const int tensor = bid >> 11;             // 0 = q, 1 = k
    const int b      = (bid >> 9) & 3;
    const int s0     = (bid & 511) << 3;
    const float* src = tensor ? kin : qin;

    // ---- stage cos/sin (8 rows x 64); completion hidden under GEMM1 ----
    {
        int r  = tid >> 4;
        int c4 = (tid & 15) << 2;
        size_t gofs = ((size_t)(b * SSS + s0 + r)) * DD + c4;
        *(float4*)&cs[r * XS_STRIDE + c4] = *(const float4*)(cosp + gofs);
        *(float4*)&ss[r * XS_STRIDE + c4] = *(const float4*)(sinp + gofs);
    }

    // ---- x row pointers: warp covers heads 4w..4w+3, row offset s0+g ----
    const float* xr0 = src + (((size_t)(b * 16 + 4*warp)) * SSS + s0 + g) * DD;
    const float* xr1 = xr0 + (size_t)SSS * DD;
    const float* xr2 = xr1 + (size_t)SSS * DD;
    const float* xr3 = xr2 + (size_t)SSS * DD;

    // ---- GEMM1: Y = X * Q^T (single-term fp16, K-permuted, A direct from GMEM) ----
    float C0[8][4], C1[8][4];
    #pragma unroll
    for (int nt = 0; nt < 8; ++nt)
        #pragma unroll
        for (int e = 0; e < 4; ++e) { C0[nt][e] = 0.0f; C1[nt][e] = 0.0f; }

    #pragma unroll
    for (int kt = 0; kt < 4; ++kt) {
        const int c0 = kt * 16 + 4 * t4;
        float4 v0a = *(const float4*)(xr0 + c0);
        float4 v0b = *(const float4*)(xr1 + c0);
        float4 v1a = *(const float4*)(xr2 + c0);
        float4 v1b = *(const float4*)(xr3 + c0);
        uint32_t a0[4], a1[4];
        a0[0] = pk_f16x2(v0a.x, v0a.y);  a0[1] = pk_f16x2(v0b.x, v0b.y);
        a0[2] = pk_f16x2(v0a.z, v0a.w);  a0[3] = pk_f16x2(v0b.z, v0b.w);
        a1[0] = pk_f16x2(v1a.x, v1a.y);  a1[1] = pk_f16x2(v1b.x, v1b.y);
        a1[2] = pk_f16x2(v1a.z, v1a.w);  a1[3] = pk_f16x2(v1b.z, v1b.w);

        #pragma unroll
        for (int nt2 = 0; nt2 < 4; ++nt2) {
            uint4 bb = B1[(kt*4 + nt2)*32 + lane];
            MMA_F16(C0[2*nt2],   a0[0], a0[1], a0[2], a0[3], bb.x, bb.y);
            MMA_F16(C0[2*nt2+1], a0[0], a0[1], a0[2], a0[3], bb.z, bb.w);
            MMA_F16(C1[2*nt2],   a1[0], a1[1], a1[2], a1[3], bb.x, bb.y);
            MMA_F16(C1[2*nt2+1], a1[0], a1[1], a1[2], a1[3], bb.z, bb.w);
        }
    }

    __syncthreads();   // cos/sin staged (hidden under GEMM1)

    // ---- rope: rows g and g+8 share s -> same cos/sin; both tiles share too ----
    {
        const float* cr = &cs[g * XS_STRIDE];
        const float* sr = &ss[g * XS_STRIDE];
        #pragma unroll
        for (int nt = 0; nt < 4; ++nt) {
            int c = 8*nt + 2*t4;
            float2 cl = *(const float2*)(cr + c);
            float2 ch = *(const float2*)(cr + c + 32);
            float2 sl = *(const float2*)(sr + c);
            float2 sh = *(const float2*)(sr + c + 32);
            #pragma unroll
            for (int e = 0; e < 4; ++e) {
                float cle = (e & 1) ? cl.y : cl.x;
                float che = (e & 1) ? ch.y : ch.x;
                float sle = (e & 1) ? sl.y : sl.x;
                float she = (e & 1) ? sh.y : sh.x;
                float ylo0 = C0[nt][e], yhi0 = C0[nt+4][e];
                C0[nt][e]   = ylo0*cle - yhi0*sle;
                C0[nt+4][e] = yhi0*che + ylo0*she;
                float ylo1 = C1[nt][e], yhi1 = C1[nt+4][e];
                C1[nt][e]   = ylo1*cle - yhi1*sle;
                C1[nt+4][e] = yhi1*che + ylo1*she;
            }
        }
    }

    // ---- Z -> A2 fragments (fp16, standard k16 layout) ----
    uint32_t A20[4][4], A21[4][4];
    #pragma unroll
    for (int kt = 0; kt < 4; ++kt) {
        A20[kt][0] = pk_f16x2(C0[2*kt][0],   C0[2*kt][1]);
        A20[kt][1] = pk_f16x2(C0[2*kt][2],   C0[2*kt][3]);
        A20[kt][2] = pk_f16x2(C0[2*kt+1][0], C0[2*kt+1][1]);
        A20[kt][3] = pk_f16x2(C0[2*kt+1][2], C0[2*kt+1][3]);
        A21[kt][0] = pk_f16x2(C1[2*kt][0],   C1[2*kt][1]);
        A21[kt][1] = pk_f16x2(C1[2*kt][2],   C1[2*kt][3]);
        A21[kt][2] = pk_f16x2(C1[2*kt+1][0], C1[2*kt+1][1]);
        A21[kt][3] = pk_f16x2(C1[2*kt+1][2], C1[2*kt+1][3]);
    }

    // ---- GEMM2: O = Z * Q ----
    #pragma unroll
    for (int nt = 0; nt < 8; ++nt)
        #pragma unroll
        for (int e = 0; e < 4; ++e) { C0[nt][e] = 0.0f; C1[nt][e] = 0.0f; }

    #pragma unroll
    for (int kt = 0; kt < 4; ++kt) {
        #pragma unroll
        for (int nt2 = 0; nt2 < 4; ++nt2) {
            uint4 bb = B2[(kt*4 + nt2)*32 + lane];
            MMA_F16(C0[2*nt2],   A20[kt][0], A20[kt][1], A20[kt][2], A20[kt][3], bb.x, bb.y);
            MMA_F16(C0[2*nt2+1], A20[kt][0], A20[kt][1], A20[kt][2], A20[kt][3], bb.z, bb.w);
            MMA_F16(C1[2*nt2],   A21[kt][0], A21[kt][1], A21[kt][2], A21[kt][3], bb.x, bb.y);
            MMA_F16(C1[2*nt2+1], A21[kt][0], A21[kt][1], A21[kt][2], A21[kt][3], bb.z, bb.w);
        }
    }

    // ---- store: fragments -> smem rows, then coalesced flush ----
    const int tb = warp * 32;
    #pragma unroll
    for (int tt = 0; tt < 2; ++tt) {
        int tbo = tb + tt * 16;
        float* o0 = &xs[(tbo + g) * XS_STRIDE];
        float* o1 = o0 + 8 * XS_STRIDE;
        #pragma unroll
        for (int nt = 0; nt < 8; ++nt) {
            int c = 8*nt + 2*t4;
            float2 v0, v1;
            if (tt == 0) { v0.x = C0[nt][0]; v0.y = C0[nt][1]; v1.x = C0[nt][2]; v1.y = C0[nt][3]; }
            else         { v0.x = C1[nt][0]; v0.y = C1[nt][1]; v1.x = C1[nt][2]; v1.y = C1[nt][3]; }
            *(float2*)(o0 + c) = v0;
            *(float2*)(o1 + c) = v1;
        }
    }
    __syncthreads();

    const size_t obase = (size_t)tensor * NROWS_Q * DD;
    #pragma unroll
    for (int it = 0; it < 16; ++it) {
        int lin = it * 128 + tid;
        int rl  = lin >> 4;
        int c4  = (lin & 15) << 2;
        int h   = rl >> 3, ds = rl & 7;
        size_t gofs = obase + (((size_t)(b * 16 + h)) * SSS + s0 + ds) * DD + c4;
        *(float4*)(out + gofs) = *(const float4*)&xs[rl * XS_STRIDE + c4];
    }
}

extern "C" void kernel_launch(void* const* d_in, const int* in_sizes, int n_in,
                              void* d_out, int out_size) {
    const float* q    = (const float*)d_in[0];
    const float* k    = (const float*)d_in[1];
    const float* cosp = (const float*)d_in[2];
    const float* sinp = (const float*)d_in[3];
    const float* vs   = (const float*)d_in[4];
    float* out = (float*)d_out;

    static bool attr_set = false;
    if (!attr_set) {
        cudaFuncSetAttribute(rnrope_fused_kernel,
                             cudaFuncAttributeMaxDynamicSharedMemorySize,
                             SMEM_FLOATS * (int)sizeof(float));
        attr_set = true;
    }
    rnrope_fused_kernel<<<NROWS_T / 128, 128, SMEM_FLOATS * sizeof(float)>>>(
        q, k, cosp, sinp, vs, out);
}

// round 15
// speedup vs baseline: 1.7788x; 1.7788x over previous
#include <cuda_runtime.h>
#include <cuda_fp16.h>
#include <cstdint>

// Shapes fixed by dataset: q/k (4,16,4096,64) f32, cos/sin (4,4096,64) f32, vs (32,64) f32
#define DD 64
#define SSS 4096
#define NROWS_Q (4*16*4096)    // 262144
#define NROWS_T (2*NROWS_Q)    // 524288
#define NREFL 32
#define NBLK (NROWS_T/128)     // 4096

// mma-ready packed fp16 B fragments in GLOBAL (written once by block 0 per launch)
// uint4 = {b0_even_nt, b1_even_nt, b0_odd_nt, b1_odd_nt}
// B1: K-permuted GEMM1 layout;  B2: standard m16n8k16 GEMM2 layout.
__device__ uint4 g_B1[512];
__device__ uint4 g_B2[512];
__device__ int g_flag = 0;             // release/acquire: B frags ready
__device__ unsigned int g_done = 0;    // completion counter (resets g_flag for next launch)

__device__ __forceinline__ uint32_t pk_f16x2(float a, float b) {
    __half2 h = __floats2half2_rn(a, b);
    return *(uint32_t*)&h;
}

#define MMA_F16(c, a0, a1, a2, a3, b0, b1)                                         \
    asm volatile("mma.sync.aligned.m16n8k16.row.col.f32.f16.f16.f32 "              \
                 "{%0,%1,%2,%3}, {%4,%5,%6,%7}, {%8,%9}, {%0,%1,%2,%3};"           \
                 : "+f"(c[0]), "+f"(c[1]), "+f"(c[2]), "+f"(c[3])                   \
                 : "r"(a0), "r"(a1), "r"(a2), "r"(a3), "r"(b0), "r"(b1))

// ---------------- single fused kernel ----------------
// Block 0: inline Householder scan -> pack B frags to global -> release flag.
// All blocks: stage cos/sin, (acquire-wait flag), R12 body.
#define XS_STRIDE 68
__global__ void __launch_bounds__(128, 4) rnrope_kernel(
    const float* __restrict__ qin, const float* __restrict__ kin,
    const float* __restrict__ cosp, const float* __restrict__ sinp,
    const float* __restrict__ vs, float* __restrict__ out)
{
    __shared__ __align__(16) float xs[128 * XS_STRIDE];   // O staging; block0 scan scratch
    __shared__ __align__(16) float cs[8 * XS_STRIDE];
    __shared__ __align__(16) float ss[8 * XS_STRIDE];
    __shared__ float coefs[NREFL];

    const int tid  = threadIdx.x;
    const int warp = tid >> 5;
    const int lane = tid & 31;
    const int g    = lane >> 2;
    const int t4   = lane & 3;

    const int bid    = blockIdx.x;            // 4096 blocks
    const int tensor = bid >> 11;             // 0 = q, 1 = k
    const int b      = (bid >> 9) & 3;
    const int s0     = (bid & 511) << 3;
    const float* src = tensor ? kin : qin;

    // ---- stage cos/sin (8 rows x 64) for ALL blocks (overlaps scan/spin) ----
    {
        int r  = tid >> 4;
        int c4 = (tid & 15) << 2;
        size_t gofs = ((size_t)(b * SSS + s0 + r)) * DD + c4;
        *(float4*)&cs[r * XS_STRIDE + c4] = *(const float4*)(cosp + gofs);
        *(float4*)&ss[r * XS_STRIDE + c4] = *(const float4*)(sinp + gofs);
    }

    if (bid == 0) {
        // ============ block 0: build Q + pack B frags to global ============
        float* vsh = xs;          // 2048 floats
        float* Qs  = xs + 2048;   // 4096 floats
        for (int i = tid; i < NREFL*DD/4; i += 128)
            ((float4*)vsh)[i] = ((const float4*)vs)[i];
        __syncthreads();
        if (tid < NREFL) {
            float s = 0.0f;
            const float4* v4 = (const float4*)&vsh[tid*DD];
            #pragma unroll
            for (int c = 0; c < 16; ++c) {
                float4 v = v4[c];
                s += v.x*v.x + v.y*v.y + v.z*v.z + v.w*v.w;
            }
            coefs[tid] = 2.0f / (s + 1e-8f);
        }
        __syncthreads();

        // column-owner scan: col j evolves independently; thread owns 32 rows of
        // one column in registers, partner (lane^16) the other 32. One shfl per r.
        const int col = (warp << 4) | (lane & 15);
        const int seg = lane >> 4;
        float qc[32];
        #pragma unroll
        for (int i = 0; i < 32; ++i) qc[i] = (seg*32 + i == col) ? 1.0f : 0.0f;

        for (int r = 0; r < NREFL; ++r) {
            const float4* v4 = (const float4*)&vsh[r*DD + seg*32];
            float4 vv[8];
            #pragma unroll
            for (int i = 0; i < 8; ++i) vv[i] = v4[i];
            float w0 = 0.f, w1 = 0.f, w2 = 0.f, w3 = 0.f;
            #pragma unroll
            for (int i = 0; i < 8; ++i) {
                w0 += vv[i].x * qc[4*i];
                w1 += vv[i].y * qc[4*i+1];
                w2 += vv[i].z * qc[4*i+2];
                w3 += vv[i].w * qc[4*i+3];
            }
            float w = (w0 + w1) + (w2 + w3);
            w += __shfl_xor_sync(0xffffffffu, w, 16);
            float cw = coefs[r] * w;
            #pragma unroll
            for (int i = 0; i < 8; ++i) {
                qc[4*i]   -= vv[i].x * cw;
                qc[4*i+1] -= vv[i].y * cw;
                qc[4*i+2] -= vv[i].z * cw;
                qc[4*i+3] -= vv[i].w * cw;
            }
        }
        #pragma unroll
        for (int i = 0; i < 32; ++i) Qs[(seg*32 + i)*DD + col] = qc[i];
        __syncthreads();

        // pack B fragments to GLOBAL
        for (int slot = tid; slot < 512; slot += 128) {
            int l2 = slot & 31, idx = slot >> 5;     // idx = kt*4 + nt2
            int kt = idx >> 2, nt2 = idx & 3;
            int gg = l2 >> 2, tt4 = l2 & 3;
            int ne = 16*nt2 + gg;
            int no = ne + 8;
            {   // B1: K-permuted, C0 = 16kt + 4t4
                int C0 = 16*kt + 4*tt4;
                uint4 v;
                v.x = pk_f16x2(Qs[ne*DD + C0],     Qs[ne*DD + C0 + 1]);
                v.y = pk_f16x2(Qs[ne*DD + C0 + 2], Qs[ne*DD + C0 + 3]);
                v.z = pk_f16x2(Qs[no*DD + C0],     Qs[no*DD + C0 + 1]);
                v.w = pk_f16x2(Qs[no*DD + C0 + 2], Qs[no*DD + C0 + 3]);
                g_B1[slot] = v;
            }
            {   // B2: standard, element (k, n) = Q[k][n]
                int k0 = 16*kt + 2*tt4;
                uint4 v;
                v.x = pk_f16x2(Qs[k0*DD + ne],     Qs[(k0+1)*DD + ne]);
                v.y = pk_f16x2(Qs[(k0+8)*DD + ne], Qs[(k0+9)*DD + ne]);
                v.z = pk_f16x2(Qs[k0*DD + no],     Qs[(k0+1)*DD + no]);
                v.w = pk_f16x2(Qs[(k0+8)*DD + no], Qs[(k0+9)*DD + no]);
                g_B2[slot] = v;
            }
        }
        __syncthreads();
        if (tid == 0) {
            __threadfence();   // frags visible device-wide before flag
            asm volatile("st.release.gpu.global.b32 [%0], %1;" :: "l"(&g_flag), "r"(1) : "memory");
        }
        __syncthreads();       // xs (scan scratch) free again
    } else {
        // ============ other blocks: acquire-wait for B frags ============
        if (tid == 0) {
            int f;
            while (true) {
                asm volatile("ld.acquire.gpu.global.b32 %0, [%1];" : "=r"(f) : "l"(&g_flag) : "memory");
                if (f) break;
                __nanosleep(128);
            }
        }
        __syncthreads();       // acquire by tid0 + barrier orders frag reads block-wide
    }

    // ================= R12 body =================
    // ---- x row pointers: warp covers heads 4w..4w+3, row offset s0+g ----
    const float* xr0 = src + (((size_t)(b * 16 + 4*warp)) * SSS + s0 + g) * DD;
    const float* xr1 = xr0 + (size_t)SSS * DD;
    const float* xr2 = xr1 + (size_t)SSS * DD;
    const float* xr3 = xr2 + (size_t)SSS * DD;

    // ---- GEMM1: Y = X * Q^T (single-term fp16, K-permuted, A direct from GMEM) ----
    float C0[8][4], C1[8][4];
    #pragma unroll
    for (int nt = 0; nt < 8; ++nt)
        #pragma unroll
        for (int e = 0; e < 4; ++e) { C0[nt][e] = 0.0f; C1[nt][e] = 0.0f; }

    #pragma unroll
    for (int kt = 0; kt < 4; ++kt) {
        const int c0 = kt * 16 + 4 * t4;
        float4 v0a = *(const float4*)(xr0 + c0);
        float4 v0b = *(const float4*)(xr1 + c0);
        float4 v1a = *(const float4*)(xr2 + c0);
        float4 v1b = *(const float4*)(xr3 + c0);
        uint32_t a0[4], a1[4];
        a0[0] = pk_f16x2(v0a.x, v0a.y);  a0[1] = pk_f16x2(v0b.x, v0b.y);
        a0[2] = pk_f16x2(v0a.z, v0a.w);  a0[3] = pk_f16x2(v0b.z, v0b.w);
        a1[0] = pk_f16x2(v1a.x, v1a.y);  a1[1] = pk_f16x2(v1b.x, v1b.y);
        a1[2] = pk_f16x2(v1a.z, v1a.w);  a1[3] = pk_f16x2(v1b.z, v1b.w);

        #pragma unroll
        for (int nt2 = 0; nt2 < 4; ++nt2) {
            uint4 bb = g_B1[(kt*4 + nt2)*32 + lane];
            MMA_F16(C0[2*nt2],   a0[0], a0[1], a0[2], a0[3], bb.x, bb.y);
            MMA_F16(C0[2*nt2+1], a0[0], a0[1], a0[2], a0[3], bb.z, bb.w);
            MMA_F16(C1[2*nt2],   a1[0], a1[1], a1[2], a1[3], bb.x, bb.y);
            MMA_F16(C1[2*nt2+1], a1[0], a1[1], a1[2], a1[3], bb.z, bb.w);
        }
    }

    __syncthreads();   // cos/sin staged (hidden under GEMM1 / scan / spin)

    // ---- rope: rows g and g+8 share s -> same cos/sin; both tiles share too ----
    {
        const float* cr = &cs[g * XS_STRIDE];
        const float* sr = &ss[g * XS_STRIDE];
        #pragma unroll
        for (int nt = 0; nt < 4; ++nt) {
            int c = 8*nt + 2*t4;
            float2 cl = *(const float2*)(cr + c);
            float2 ch = *(const float2*)(cr + c + 32);
            float2 sl = *(const float2*)(sr + c);
            float2 sh = *(const float2*)(sr + c + 32);
            #pragma unroll
            for (int e = 0; e < 4; ++e) {
                float cle = (e & 1) ? cl.y : cl.x;
                float che = (e & 1) ? ch.y : ch.x;
                float sle = (e & 1) ? sl.y : sl.x;
                float she = (e & 1) ? sh.y : sh.x;
                float ylo0 = C0[nt][e], yhi0 = C0[nt+4][e];
                C0[nt][e]   = ylo0*cle - yhi0*sle;
                C0[nt+4][e] = yhi0*che + ylo0*she;
                float ylo1 = C1[nt][e], yhi1 = C1[nt+4][e];
                C1[nt][e]   = ylo1*cle - yhi1*sle;
                C1[nt+4][e] = yhi1*che + ylo1*she;
            }
        }
    }

    // ---- Z -> A2 fragments (fp16, standard k16 layout) ----
    uint32_t A20[4][4], A21[4][4];
    #pragma unroll
    for (int kt = 0; kt < 4; ++kt) {
        A20[kt][0] = pk_f16x2(C0[2*kt][0],   C0[2*kt][1]);
        A20[kt][1] = pk_f16x2(C0[2*kt][2],   C0[2*kt][3]);
        A20[kt][2] = pk_f16x2(C0[2*kt+1][0], C0[2*kt+1][1]);
        A20[kt][3] = pk_f16x2(C0[2*kt+1][2], C0[2*kt+1][3]);
        A21[kt][0] = pk_f16x2(C1[2*kt][0],   C1[2*kt][1]);
        A21[kt][1] = pk_f16x2(C1[2*kt][2],   C1[2*kt][3]);
        A21[kt][2] = pk_f16x2(C1[2*kt+1][0], C1[2*kt+1][1]);
        A21[kt][3] = pk_f16x2(C1[2*kt+1][2], C1[2*kt+1][3]);
    }

    // ---- GEMM2: O = Z * Q ----
    #pragma unroll
    for (int nt = 0; nt < 8; ++nt)
        #pragma unroll
        for (int e = 0; e < 4; ++e) { C0[nt][e] = 0.0f; C1[nt][e] = 0.0f; }

    #pragma unroll
    for (int kt = 0; kt < 4; ++kt) {
        #pragma unroll
        for (int nt2 = 0; nt2 < 4; ++nt2) {
            uint4 bb = g_B2[(kt*4 + nt2)*32 + lane];
            MMA_F16(C0[2*nt2],   A20[kt][0], A20[kt][1], A20[kt][2], A20[kt][3], bb.x, bb.y);
            MMA_F16(C0[2*nt2+1], A20[kt][0], A20[kt][1], A20[kt][2], A20[kt][3], bb.z, bb.w);
            MMA_F16(C1[2*nt2],   A21[kt][0], A21[kt][1], A21[kt][2], A21[kt][3], bb.x, bb.y);
            MMA_F16(C1[2*nt2+1], A21[kt][0], A21[kt][1], A21[kt][2], A21[kt][3], bb.z, bb.w);
        }
    }

    // ---- store: fragments -> smem rows, then coalesced flush ----
    const int tb = warp * 32;
    #pragma unroll
    for (int tt = 0; tt < 2; ++tt) {
        int tbo = tb + tt * 16;
        float* o0 = &xs[(tbo + g) * XS_STRIDE];
        float* o1 = o0 + 8 * XS_STRIDE;
        #pragma unroll
        for (int nt = 0; nt < 8; ++nt) {
            int c = 8*nt + 2*t4;
            float2 v0, v1;
            if (tt == 0) { v0.x = C0[nt][0]; v0.y = C0[nt][1]; v1.x = C0[nt][2]; v1.y = C0[nt][3]; }
            else         { v0.x = C1[nt][0]; v0.y = C1[nt][1]; v1.x = C1[nt][2]; v1.y = C1[nt][3]; }
            *(float2*)(o0 + c) = v0;
            *(float2*)(o1 + c) = v1;
        }
    }
    __syncthreads();

    const size_t obase = (size_t)tensor * NROWS_Q * DD;
    #pragma unroll
    for (int it = 0; it < 16; ++it) {
        int lin = it * 128 + tid;
        int rl  = lin >> 4;
        int c4  = (lin & 15) << 2;
        int h   = rl >> 3, ds = rl & 7;
        size_t gofs = obase + (((size_t)(b * 16 + h)) * SSS + s0 + ds) * DD + c4;
        *(float4*)(out + gofs) = *(const float4*)&xs[rl * XS_STRIDE + c4];
    }

    // ---- per-launch reset so every call does identical work (no cross-call caching) ----
    if (tid == 0) {
        unsigned int d = atomicAdd(&g_done, 1u);
        if (d == NBLK - 1) {           // last block to finish resets for next launch
            g_done = 0;
            __threadfence();
            g_flag = 0;
        }
    }
}

extern "C" void kernel_launch(void* const* d_in, const int* in_sizes, int n_in,
                              void* d_out, int out_size) {
    const float* q    = (const float*)d_in[0];
    const float* k    = (const float*)d_in[1];
    const float* cosp = (const float*)d_in[2];
    const float* sinp = (const float*)d_in[3];
    const float* vs   = (const float*)d_in[4];
    float* out = (float*)d_out;

    rnrope_kernel<<<NBLK, 128>>>(q, k, cosp, sinp, vs, out);
}

// round 16
// speedup vs baseline: 1.9715x; 1.1084x over previous
#include <cuda_runtime.h>
#include <cuda_fp16.h>
#include <cstdint>

// Shapes fixed by dataset: q/k (4,16,4096,64) f32, cos/sin (4,4096,64) f32, vs (32,64) f32
#define DD 64
#define SSS 4096
#define NROWS_Q (4*16*4096)    // 262144
#define NROWS_T (2*NROWS_Q)    // 524288
#define NREFL 32
#define NBLK (NROWS_T/128)     // 4096

// mma-ready packed fp16 B fragments, uint4 = {b0_even_nt, b1_even_nt, b0_odd_nt, b1_odd_nt}
// B1: K-permuted GEMM1 layout (thread t4 owns contiguous cols 16kt+4t4..+3)
// B2: standard m16n8k16 layout (k0 = 16kt+2t4, pairs (k0,k0+1),(k0+8,k0+9))
__device__ uint4 g_B1[512];
__device__ uint4 g_B2[512];

__device__ __forceinline__ uint32_t pk_f16x2(float a, float b) {
    __half2 h = __floats2half2_rn(a, b);
    return *(uint32_t*)&h;
}

#define MMA_F16(c, a0, a1, a2, a3, b0, b1)                                         \
    asm volatile("mma.sync.aligned.m16n8k16.row.col.f32.f16.f16.f32 "              \
                 "{%0,%1,%2,%3}, {%4,%5,%6,%7}, {%8,%9}, {%0,%1,%2,%3};"           \
                 : "+f"(c[0]), "+f"(c[1]), "+f"(c[2]), "+f"(c[3])                   \
                 : "r"(a0), "r"(a1), "r"(a2), "r"(a3), "r"(b0), "r"(b1))

// ---------------- Kernel A: build Q (barrier-free column-owner scan) + pack B ----------------
__global__ void build_q_kernel(const float* __restrict__ vs) {
    __shared__ __align__(16) float vsh[NREFL*DD];
    __shared__ float coefs[NREFL];
    __shared__ float Qs[DD*DD];
    const int tid  = threadIdx.x;       // 256
    const int lane = tid & 31;
    const int warp = tid >> 5;

    for (int i = tid; i < NREFL*DD/4; i += 256)
        ((float4*)vsh)[i] = ((const float4*)vs)[i];
    __syncthreads();
    if (tid < NREFL) {
        float s = 0.0f;
        const float4* v4 = (const float4*)&vsh[tid*DD];
        #pragma unroll
        for (int c = 0; c < 16; ++c) {
            float4 v = v4[c];
            s += v.x*v.x + v.y*v.y + v.z*v.z + v.w*v.w;
        }
        coefs[tid] = 2.0f / (s + 1e-8f);
    }
    __syncthreads();

    if (warp < 4) {
        const int col = (warp << 4) | (lane & 15);
        const int seg = lane >> 4;
        float qc[32];
        #pragma unroll
        for (int i = 0; i < 32; ++i) qc[i] = (seg*32 + i == col) ? 1.0f : 0.0f;

        for (int r = 0; r < NREFL; ++r) {
            const float4* v4 = (const float4*)&vsh[r*DD + seg*32];
            float4 vv[8];
            #pragma unroll
            for (int i = 0; i < 8; ++i) vv[i] = v4[i];
            float w0 = 0.f, w1 = 0.f, w2 = 0.f, w3 = 0.f;
            #pragma unroll
            for (int i = 0; i < 8; ++i) {
                w0 += vv[i].x * qc[4*i];
                w1 += vv[i].y * qc[4*i+1];
                w2 += vv[i].z * qc[4*i+2];
                w3 += vv[i].w * qc[4*i+3];
            }
            float w = (w0 + w1) + (w2 + w3);
            w += __shfl_xor_sync(0xffffffffu, w, 16);
            float cw = coefs[r] * w;
            #pragma unroll
            for (int i = 0; i < 8; ++i) {
                qc[4*i]   -= vv[i].x * cw;
                qc[4*i+1] -= vv[i].y * cw;
                qc[4*i+2] -= vv[i].z * cw;
                qc[4*i+3] -= vv[i].w * cw;
            }
        }
        #pragma unroll
        for (int i = 0; i < 32; ++i) Qs[(seg*32 + i)*DD + col] = qc[i];
    }
    __syncthreads();

    // pack B fragments (fp16, uint4 pairs of nt)
    for (int slot = tid; slot < 512; slot += 256) {
        int l2 = slot & 31, idx = slot >> 5;     // idx = kt*4 + nt2
        int kt = idx >> 2, nt2 = idx & 3;
        int gg = l2 >> 2, tt4 = l2 & 3;
        int ne = 16*nt2 + gg;
        int no = ne + 8;
        {   // B1: K-permuted, C0 = 16kt + 4t4
            int C0 = 16*kt + 4*tt4;
            uint4 v;
            v.x = pk_f16x2(Qs[ne*DD + C0],     Qs[ne*DD + C0 + 1]);
            v.y = pk_f16x2(Qs[ne*DD + C0 + 2], Qs[ne*DD + C0 + 3]);
            v.z = pk_f16x2(Qs[no*DD + C0],     Qs[no*DD + C0 + 1]);
            v.w = pk_f16x2(Qs[no*DD + C0 + 2], Qs[no*DD + C0 + 3]);
            g_B1[slot] = v;
        }
        {   // B2: standard, element (k, n) = Q[k][n]
            int k0 = 16*kt + 2*tt4;
            uint4 v;
            v.x = pk_f16x2(Qs[k0*DD + ne],     Qs[(k0+1)*DD + ne]);
            v.y = pk_f16x2(Qs[(k0+8)*DD + ne], Qs[(k0+9)*DD + ne]);
            v.z = pk_f16x2(Qs[k0*DD + no],     Qs[(k0+1)*DD + no]);
            v.w = pk_f16x2(Qs[(k0+8)*DD + no], Qs[(k0+9)*DD + no]);
            g_B2[slot] = v;
        }
    }
    __syncthreads();

    // PDL: fragments written; allow the dependent grid to proceed past its
    // cudaGridDependencySynchronize(). Memory written before the trigger is
    // visible to the secondary grid after it synchronizes.
    if (tid == 0) __threadfence();
    __syncthreads();
    cudaTriggerProgrammaticLaunchCompletion();
}

// ---------------- Kernel B: R12 body + grid-dependency sync ----------------
// Block = 128 threads (4 warps), ONE (tensor, b, s-chunk of 8) x 16 heads = 128 rows.
// Each warp: TWO 16-row M-tiles. A1 direct from GMEM (K-permuted GEMM1);
// rope applied in C fragments; GEMM2 from register A2; O via smem flush.
#define XS_STRIDE 68
__global__ void __launch_bounds__(128, 4) rnrope_mma_kernel(
    const float* __restrict__ qin, const float* __restrict__ kin,
    const float* __restrict__ cosp, const float* __restrict__ sinp,
    float* __restrict__ out)
{
    __shared__ __align__(16) float xs[128 * XS_STRIDE];   // O staging
    __shared__ __align__(16) float cs[8 * XS_STRIDE];
    __shared__ __align__(16) float ss[8 * XS_STRIDE];

    const int tid  = threadIdx.x;
    const int warp = tid >> 5;
    const int lane = tid & 31;
    const int g    = lane >> 2;
    const int t4   = lane & 3;

    const int bid    = blockIdx.x;            // 4096 blocks
    const int tensor = bid >> 11;             // 0 = q, 1 = k
    const int b      = (bid >> 9) & 3;
    const int s0     = (bid & 511) << 3;
    const float* src = tensor ? kin : qin;

    // ---- preamble (independent of build_q): stage cos/sin ----
    {
        int r  = tid >> 4;
        int c4 = (tid & 15) << 2;
        size_t gofs = ((size_t)(b * SSS + s0 + r)) * DD + c4;
        *(float4*)&cs[r * XS_STRIDE + c4] = *(const float4*)(cosp + gofs);
        *(float4*)&ss[r * XS_STRIDE + c4] = *(const float4*)(sinp + gofs);
    }

    // ---- x row pointers: warp covers heads 4w..4w+3, row offset s0+g ----
    const float* xr0 = src + (((size_t)(b * 16 + 4*warp)) * SSS + s0 + g) * DD;
    const float* xr1 = xr0 + (size_t)SSS * DD;
    const float* xr2 = xr1 + (size_t)SSS * DD;
    const float* xr3 = xr2 + (size_t)SSS * DD;

    // ---- wait for build_q's fragments (HW grid dependency, not a spin) ----
    cudaGridDependencySynchronize();

    // ---- GEMM1: Y = X * Q^T (single-term fp16, K-permuted, A direct from GMEM) ----
    float C0[8][4], C1[8][4];
    #pragma unroll
    for (int nt = 0; nt < 8; ++nt)
        #pragma unroll
        for (int e = 0; e < 4; ++e) { C0[nt][e] = 0.0f; C1[nt][e] = 0.0f; }

    #pragma unroll
    for (int kt = 0; kt < 4; ++kt) {
        const int c0 = kt * 16 + 4 * t4;
        float4 v0a = *(const float4*)(xr0 + c0);
        float4 v0b = *(const float4*)(xr1 + c0);
        float4 v1a = *(const float4*)(xr2 + c0);
        float4 v1b = *(const float4*)(xr3 + c0);
        uint32_t a0[4], a1[4];
        a0[0] = pk_f16x2(v0a.x, v0a.y);  a0[1] = pk_f16x2(v0b.x, v0b.y);
        a0[2] = pk_f16x2(v0a.z, v0a.w);  a0[3] = pk_f16x2(v0b.z, v0b.w);
        a1[0] = pk_f16x2(v1a.x, v1a.y);  a1[1] = pk_f16x2(v1b.x, v1b.y);
        a1[2] = pk_f16x2(v1a.z, v1a.w);  a1[3] = pk_f16x2(v1b.z, v1b.w);

        #pragma unroll
        for (int nt2 = 0; nt2 < 4; ++nt2) {
            uint4 bb = g_B1[(kt*4 + nt2)*32 + lane];
            MMA_F16(C0[2*nt2],   a0[0], a0[1], a0[2], a0[3], bb.x, bb.y);
            MMA_F16(C0[2*nt2+1], a0[0], a0[1], a0[2], a0[3], bb.z, bb.w);
            MMA_F16(C1[2*nt2],   a1[0], a1[1], a1[2], a1[3], bb.x, bb.y);
            MMA_F16(C1[2*nt2+1], a1[0], a1[1], a1[2], a1[3], bb.z, bb.w);
        }
    }

    __syncthreads();   // cos/sin staged (hidden under GEMM1)

    // ---- rope: rows g and g+8 share s -> same cos/sin; both tiles share too ----
    {
        const float* cr = &cs[g * XS_STRIDE];
        const float* sr = &ss[g * XS_STRIDE];
        #pragma unroll
        for (int nt = 0; nt < 4; ++nt) {
            int c = 8*nt + 2*t4;
            float2 cl = *(const float2*)(cr + c);
            float2 ch = *(const float2*)(cr + c + 32);
            float2 sl = *(const float2*)(sr + c);
            float2 sh = *(const float2*)(sr + c + 32);
            #pragma unroll
            for (int e = 0; e < 4; ++e) {
                float cle = (e & 1) ? cl.y : cl.x;
                float che = (e & 1) ? ch.y : ch.x;
                float sle = (e & 1) ? sl.y : sl.x;
                float she = (e & 1) ? sh.y : sh.x;
                float ylo0 = C0[nt][e], yhi0 = C0[nt+4][e];
                C0[nt][e]   = ylo0*cle - yhi0*sle;
                C0[nt+4][e] = yhi0*che + ylo0*she;
                float ylo1 = C1[nt][e], yhi1 = C1[nt+4][e];
                C1[nt][e]   = ylo1*cle - yhi1*sle;
                C1[nt+4][e] = yhi1*che + ylo1*she;
            }
        }
    }

    // ---- Z -> A2 fragments (fp16, standard k16 layout) ----
    uint32_t A20[4][4], A21[4][4];
    #pragma unroll
    for (int kt = 0; kt < 4; ++kt) {
        A20[kt][0] = pk_f16x2(C0[2*kt][0],   C0[2*kt][1]);
        A20[kt][1] = pk_f16x2(C0[2*kt][2],   C0[2*kt][3]);
        A20[kt][2] = pk_f16x2(C0[2*kt+1][0], C0[2*kt+1][1]);
        A20[kt][3] = pk_f16x2(C0[2*kt+1][2], C0[2*kt+1][3]);
        A21[kt][0] = pk_f16x2(C1[2*kt][0],   C1[2*kt][1]);
        A21[kt][1] = pk_f16x2(C1[2*kt][2],   C1[2*kt][3]);
        A21[kt][2] = pk_f16x2(C1[2*kt+1][0], C1[2*kt+1][1]);
        A21[kt][3] = pk_f16x2(C1[2*kt+1][2], C1[2*kt+1][3]);
    }

    // ---- GEMM2: O = Z * Q ----
    #pragma unroll
    for (int nt = 0; nt < 8; ++nt)
        #pragma unroll
        for (int e = 0; e < 4; ++e) { C0[nt][e] = 0.0f; C1[nt][e] = 0.0f; }

    #pragma unroll
    for (int kt = 0; kt < 4; ++kt) {
        #pragma unroll
        for (int nt2 = 0; nt2 < 4; ++nt2) {
            uint4 bb = g_B2[(kt*4 + nt2)*32 + lane];
            MMA_F16(C0[2*nt2],   A20[kt][0], A20[kt][1], A20[kt][2], A20[kt][3], bb.x, bb.y);
            MMA_F16(C0[2*nt2+1], A20[kt][0], A20[kt][1], A20[kt][2], A20[kt][3], bb.z, bb.w);
            MMA_F16(C1[2*nt2],   A21[kt][0], A21[kt][1], A21[kt][2], A21[kt][3], bb.x, bb.y);
            MMA_F16(C1[2*nt2+1], A21[kt][0], A21[kt][1], A21[kt][2], A21[kt][3], bb.z, bb.w);
        }
    }

    // ---- store: fragments -> smem rows, then coalesced flush ----
    const int tb = warp * 32;
    #pragma unroll
    for (int tt = 0; tt < 2; ++tt) {
        int tbo = tb + tt * 16;
        float* o0 = &xs[(tbo + g) * XS_STRIDE];
        float* o1 = o0 + 8 * XS_STRIDE;
        #pragma unroll
        for (int nt = 0; nt < 8; ++nt) {
            int c = 8*nt + 2*t4;
            float2 v0, v1;
            if (tt == 0) { v0.x = C0[nt][0]; v0.y = C0[nt][1]; v1.x = C0[nt][2]; v1.y = C0[nt][3]; }
            else         { v0.x = C1[nt][0]; v0.y = C1[nt][1]; v1.x = C1[nt][2]; v1.y = C1[nt][3]; }
            *(float2*)(o0 + c) = v0;
            *(float2*)(o1 + c) = v1;
        }
    }
    __syncthreads();

    const size_t obase = (size_t)tensor * NROWS_Q * DD;
    #pragma unroll
    for (int it = 0; it < 16; ++it) {
        int lin = it * 128 + tid;
        int rl  = lin >> 4;
        int c4  = (lin & 15) << 2;
        int h   = rl >> 3, ds = rl & 7;
        size_t gofs = obase + (((size_t)(b * 16 + h)) * SSS + s0 + ds) * DD + c4;
        *(float4*)(out + gofs) = *(const float4*)&xs[rl * XS_STRIDE + c4];
    }
}

extern "C" void kernel_launch(void* const* d_in, const int* in_sizes, int n_in,
                              void* d_out, int out_size) {
    const float* q    = (const float*)d_in[0];
    const float* k    = (const float*)d_in[1];
    const float* cosp = (const float*)d_in[2];
    const float* sinp = (const float*)d_in[3];
    const float* vs   = (const float*)d_in[4];
    float* out = (float*)d_out;

    build_q_kernel<<<1, 256>>>(vs);

    // PDL launch: main kernel may begin its preamble while build_q is still
    // running; cudaGridDependencySynchronize() inside gates the B-frag reads.
    cudaLaunchAttribute attrs[1];
    attrs[0].id = cudaLaunchAttributeProgrammaticStreamSerialization;
    attrs[0].val.programmaticStreamSerializationAllowed = 1;
    cudaLaunchConfig_t cfg = {};
    cfg.gridDim  = dim3(NBLK, 1, 1);
    cfg.blockDim = dim3(128, 1, 1);
    cfg.dynamicSmemBytes = 0;
    cfg.stream = 0;
    cfg.attrs = attrs;
    cfg.numAttrs = 1;
    cudaLaunchKernelEx(&cfg, rnrope_mma_kernel, q, k, cosp, sinp, out);
}